// round 1
// baseline (speedup 1.0000x reference)
#include <cuda_runtime.h>
#include <cuda_fp16.h>
#include <math.h>
#include <stdint.h>

// Problem constants
#define LSEQ  4096
#define NFFT  8192
#define NBINS 512          // frequencies kept: f < N_PARTIAL/2 = 512
#define BH    6144         // B*H = 8*768
#define HDIM  768
#define M1    6912         // BH + HDIM (k rows ride along in GEMM1)
#define K1    4096
#define N1    1024         // 512 bins x (re, im)
#define M2    6144
#define K2    1024
#define N2    4096

// ---------------- scratch (static device globals; no allocs allowed) --------
__device__ __align__(16) __half g_A [(size_t)M1 * K1];   // fp16 inputs [x ; k]
__device__ __align__(16) __half g_Wf[(size_t)K1 * N1];   // forward DFT weights
__device__ __align__(16) float  g_X [(size_t)M1 * N1];   // spectra (x rows, then k rows)
__device__ __align__(16) __half g_Z [(size_t)M2 * K2];   // scaled product spectrum
__device__ __align__(16) __half g_Wi[(size_t)K2 * N2];   // inverse DFT weights
__device__ float g_tab[NFFT];                            // cos(2*pi*i/8192)

// ---------------- small PTX helpers ----------------------------------------
__device__ __forceinline__ uint32_t smem_u32(const void* p) {
    return (uint32_t)__cvta_generic_to_shared(p);
}
__device__ __forceinline__ void cp16(uint32_t dst, const void* src) {
    asm volatile("cp.async.cg.shared.global [%0], [%1], 16;\n" :: "r"(dst), "l"(src));
}
__device__ __forceinline__ void cp_commit() {
    asm volatile("cp.async.commit_group;\n" ::: "memory");
}
template <int N>
__device__ __forceinline__ void cp_wait() {
    asm volatile("cp.async.wait_group %0;\n" :: "n"(N) : "memory");
}
__device__ __forceinline__ void ldsm4(uint32_t& r0, uint32_t& r1, uint32_t& r2, uint32_t& r3, uint32_t a) {
    asm volatile("ldmatrix.sync.aligned.m8n8.x4.shared.b16 {%0,%1,%2,%3}, [%4];\n"
                 : "=r"(r0), "=r"(r1), "=r"(r2), "=r"(r3) : "r"(a));
}
__device__ __forceinline__ void ldsm4t(uint32_t& r0, uint32_t& r1, uint32_t& r2, uint32_t& r3, uint32_t a) {
    asm volatile("ldmatrix.sync.aligned.m8n8.x4.trans.shared.b16 {%0,%1,%2,%3}, [%4];\n"
                 : "=r"(r0), "=r"(r1), "=r"(r2), "=r"(r3) : "r"(a));
}
__device__ __forceinline__ void mma16816(float* c, uint32_t a0, uint32_t a1, uint32_t a2, uint32_t a3,
                                         uint32_t b0, uint32_t b1) {
    asm volatile(
        "mma.sync.aligned.m16n8k16.row.col.f32.f16.f16.f32 "
        "{%0,%1,%2,%3}, {%4,%5,%6,%7}, {%8,%9}, {%0,%1,%2,%3};\n"
        : "+f"(c[0]), "+f"(c[1]), "+f"(c[2]), "+f"(c[3])
        : "r"(a0), "r"(a1), "r"(a2), "r"(a3), "r"(b0), "r"(b1));
}

// ---------------- setup kernels ---------------------------------------------
__global__ void build_table() {
    int i = blockIdx.x * 256 + threadIdx.x;                 // i < 8192
    g_tab[i] = (float)cos(6.283185307179586476925286766559 * (double)i / 8192.0);
}

// A = [x (6144 rows) ; k (768 rows)] as fp16, 2 elements/thread
__global__ void convert_inputs(const float2* __restrict__ x2, const float2* __restrict__ k2) {
    size_t i = (size_t)blockIdx.x * 256 + threadIdx.x;      // i < M1*K1/2
    const size_t XN2 = (size_t)BH * LSEQ / 2;
    float2 v = (i < XN2) ? x2[i] : k2[i - XN2];
    ((__half2*)g_A)[i] = __floats2half2_rn(v.x, v.y);
}

// Wf[n][2f] = cos(2*pi*f*n/8192), Wf[n][2f+1] = -sin(...) = tab[(m+2048)&8191]
__global__ void fill_Wf() {
    int idx = blockIdx.x * 256 + threadIdx.x;               // idx < K1*NBINS
    int n = idx >> 9, f = idx & 511;
    int m = (f * n) & (NFFT - 1);
    __half c = __float2half_rn(g_tab[m]);
    __half s = __float2half_rn(g_tab[(m + 2048) & (NFFT - 1)]);
    ((__half2*)g_Wf)[(size_t)n * (N1 / 2) + f] = __halves2half2(c, s);
}

// Wi[2f][n] = cos(theta), Wi[2f+1][n] = +sin(theta) = tab[(m+6144)&8191]
__global__ void fill_Wi() {
    int idx = blockIdx.x * 256 + threadIdx.x;               // idx < NBINS*N2
    int f = idx >> 12, n = idx & 4095;
    int m = (f * n) & (NFFT - 1);
    g_Wi[(size_t)(2 * f) * N2 + n]     = __float2half_rn(g_tab[m]);
    g_Wi[(size_t)(2 * f + 1) * N2 + n] = __float2half_rn(g_tab[(m + 6144) & (NFFT - 1)]);
}

// Z = alpha * X*K  stored as (Zr, -Zi) fp16;  alpha = 2/8192 (1/8192 at f=0)
__global__ void pointwise_mul() {
    int idx = blockIdx.x * 256 + threadIdx.x;               // idx < BH*NBINS
    int r = idx >> 9, f = idx & 511;
    int h = r % HDIM;
    float2 X = ((const float2*)g_X)[(size_t)r * NBINS + f];
    float2 K = ((const float2*)g_X)[(size_t)(BH + h) * NBINS + f];
    float alpha = (f == 0) ? (1.0f / 8192.0f) : (2.0f / 8192.0f);
    float Zr =  alpha * (X.x * K.x - X.y * K.y);
    float Zi =  alpha * (X.x * K.y + X.y * K.x);
    ((__half2*)g_Z)[(size_t)r * NBINS + f] = __floats2half2_rn(Zr, -Zi);
}

// ---------------- fp16 GEMM: C[M,N] = A[M,K] @ B[K,N], fp32 accumulate ------
// 128x128x32 tiles, 256 threads (8 warps as 4x2, each warp 32x64),
// cp.async double buffering, ldmatrix fragments, mma.m16n8k16.
template <int MM, int NN, int KK, int WHICH>
__global__ void __launch_bounds__(256, 2) gemm_f16(float* __restrict__ outp) {
    const __half* __restrict__ A = (WHICH == 1) ? g_A  : g_Z;
    const __half* __restrict__ B = (WHICH == 1) ? g_Wf : g_Wi;
    float* __restrict__ C        = (WHICH == 1) ? g_X  : outp;

    constexpr int BM = 128, BN = 128, BK = 32;
    constexpr int LDA = BK + 8;   // 40 halves -> 80B rows (conflict-free for ldmatrix)
    constexpr int LDB = BN + 8;   // 136 halves -> 272B rows (conflict-free)
    __shared__ __align__(16) __half As[2][BM * LDA];
    __shared__ __align__(16) __half Bs[2][BK * LDB];

    const int tid = threadIdx.x, lane = tid & 31, wid = tid >> 5;
    const int wm = wid & 3, wn = wid >> 2;
    const int bm = blockIdx.y * BM, bn = blockIdx.x * BN;

    float acc[2][8][4];
#pragma unroll
    for (int i = 0; i < 2; i++)
#pragma unroll
        for (int j = 0; j < 8; j++)
#pragma unroll
            for (int q = 0; q < 4; q++) acc[i][j][q] = 0.f;

    const int arow = tid >> 2, acol = (tid & 3) << 3;   // A: 4 x 16B chunks per row
    const int brow = tid >> 4, bcol = (tid & 15) << 3;  // B: 16 x 16B chunks per row

    auto load_tile = [&](int kt, int buf) {
        const int k0 = kt * BK;
        const __half* ag = A + (size_t)(bm + arow) * KK + k0 + acol;
        cp16(smem_u32(&As[buf][arow * LDA + acol]), ag);
        cp16(smem_u32(&As[buf][(arow + 64) * LDA + acol]), ag + (size_t)64 * KK);
        const __half* bg = B + (size_t)(k0 + brow) * NN + bn + bcol;
        cp16(smem_u32(&Bs[buf][brow * LDB + bcol]), bg);
        cp16(smem_u32(&Bs[buf][(brow + 16) * LDB + bcol]), bg + (size_t)16 * NN);
        cp_commit();
    };

    load_tile(0, 0);

    constexpr int KT = KK / BK;
    for (int kt = 0; kt < KT; kt++) {
        const int buf = kt & 1;
        if (kt + 1 < KT) { load_tile(kt + 1, buf ^ 1); cp_wait<1>(); }
        else            { cp_wait<0>(); }
        __syncthreads();

#pragma unroll
        for (int ks = 0; ks < 2; ks++) {
            uint32_t a[2][4], b[4][4];
#pragma unroll
            for (int mt = 0; mt < 2; mt++) {
                int r = wm * 32 + mt * 16 + (lane & 15);
                int c = ks * 16 + ((lane >> 4) << 3);
                ldsm4(a[mt][0], a[mt][1], a[mt][2], a[mt][3], smem_u32(&As[buf][r * LDA + c]));
            }
#pragma unroll
            for (int nt = 0; nt < 4; nt++) {
                int r = ks * 16 + (lane & 15);
                int c = wn * 64 + nt * 16 + ((lane >> 4) << 3);
                ldsm4t(b[nt][0], b[nt][1], b[nt][2], b[nt][3], smem_u32(&Bs[buf][r * LDB + c]));
            }
#pragma unroll
            for (int mt = 0; mt < 2; mt++)
#pragma unroll
                for (int nt = 0; nt < 8; nt++)
                    mma16816(acc[mt][nt], a[mt][0], a[mt][1], a[mt][2], a[mt][3],
                             b[nt >> 1][(nt & 1) * 2], b[nt >> 1][(nt & 1) * 2 + 1]);
        }
        __syncthreads();
    }

#pragma unroll
    for (int mt = 0; mt < 2; mt++) {
#pragma unroll
        for (int nt = 0; nt < 8; nt++) {
            int row = bm + wm * 32 + mt * 16 + (lane >> 2);
            int col = bn + wn * 64 + nt * 8 + ((lane & 3) << 1);
            C[(size_t)row * NN + col]         = acc[mt][nt][0];
            C[(size_t)row * NN + col + 1]     = acc[mt][nt][1];
            C[(size_t)(row + 8) * NN + col]     = acc[mt][nt][2];
            C[(size_t)(row + 8) * NN + col + 1] = acc[mt][nt][3];
        }
    }
}

// ---------------- launch -----------------------------------------------------
extern "C" void kernel_launch(void* const* d_in, const int* in_sizes, int n_in,
                              void* d_out, int out_size) {
    const float2* x2 = (const float2*)d_in[0];   // x: [8,768,4096] fp32
    const float2* k2 = (const float2*)d_in[1];   // k: [768,4096]  fp32
    float* out = (float*)d_out;                  // y: [8,768,4096] fp32

    build_table<<<NFFT / 256, 256>>>();
    convert_inputs<<<(M1 * K1 / 2) / 256, 256>>>(x2, k2);
    fill_Wf<<<(K1 * NBINS) / 256, 256>>>();
    fill_Wi<<<(NBINS * N2) / 256, 256>>>();

    // GEMM1: spectra of x rows and k rows in one shot
    gemm_f16<M1, N1, K1, 1><<<dim3(N1 / 128, M1 / 128), 256>>>(nullptr);

    pointwise_mul<<<(BH * NBINS) / 256, 256>>>();

    // GEMM2: inverse transform straight into d_out
    gemm_f16<M2, N2, K2, 2><<<dim3(N2 / 128, M2 / 128), 256>>>(out);
}

// round 3
// speedup vs baseline: 2.0655x; 2.0655x over previous
#include <cuda_runtime.h>
#include <cuda_fp16.h>
#include <math.h>
#include <stdint.h>

// ---------------- problem constants -----------------------------------------
#define LSEQ  4096
#define NFFT  8192
#define NBINS 512          // kept frequencies: f < 512
#define BH    6144         // B*H
#define HDIM  768
#define M1    6912         // BH + HDIM (k rows ride along in GEMM1)
#define K1    4096
#define N1    1024         // 512 bins x (re, im)
#define M2    6144
#define K2    1024
#define N2    4096

// Does this device-compilation pass have sm_103a features (tcgen05/TMEM)?
#if defined(__CUDA_ARCH__) && (__CUDA_ARCH__ >= 1000) && \
    (defined(__CUDA_ARCH_FEAT_SM103_ALL) || defined(__CUDA_ARCH_SPECIFIC__) || \
     defined(__CUDA_ARCH_FAMILY_SPECIFIC__))
#define HAS_TCGEN05 1
#else
#define HAS_TCGEN05 0
#endif

// ---------------- device scratch (no allocs allowed) ------------------------
__device__ __align__(16) __half g_A [(size_t)M1 * K1];   // [M1,K1] inputs [x ; k]
__device__ __align__(16) __half g_Wf[(size_t)N1 * K1];   // [N1,K1] fwd DFT weights (K-major)
__device__ __align__(16) float  g_X [(size_t)M1 * N1];   // spectra
__device__ __align__(16) __half g_Z [(size_t)M2 * K2];   // scaled product spectrum
__device__ __align__(16) __half g_Wi[(size_t)N2 * K2];   // [N2,K2] inv DFT weights (K-major)
__device__ float g_tab[NFFT];

// ---------------- generic PTX helpers ----------------------------------------
__device__ __forceinline__ uint32_t smem_u32(const void* p) {
    return (uint32_t)__cvta_generic_to_shared(p);
}
__device__ __forceinline__ void cp16(uint32_t dst, const void* src) {
    asm volatile("cp.async.cg.shared.global [%0], [%1], 16;\n" :: "r"(dst), "l"(src));
}
__device__ __forceinline__ void cp_commit() {
    asm volatile("cp.async.commit_group;\n" ::: "memory");
}
template <int N>
__device__ __forceinline__ void cp_wait() {
    asm volatile("cp.async.wait_group %0;\n" :: "n"(N) : "memory");
}
#define SWZ(off) ((off) ^ (((off) >> 3) & 0x70))

#define MBARRIER_INIT(mbar, count) \
    asm volatile("mbarrier.init.shared.b64 [%0], %1;" :: "r"((uint32_t)(mbar)), "r"((uint32_t)(count)) : "memory")
#define MBARRIER_ARRIVE(mbar) \
    asm volatile("mbarrier.arrive.shared.b64 _, [%0];" :: "r"((uint32_t)(mbar)) : "memory")
#define MBARRIER_WAIT_PARITY(mbar, parity) do {                                   \
    uint32_t _m = (uint32_t)(mbar); uint32_t _p = (uint32_t)(parity); uint32_t _d; \
    asm volatile("{\n\t.reg .pred p;\n\t"                                         \
        "mbarrier.try_wait.parity.acquire.cta.shared::cta.b64 p, [%1], %2;\n\t"   \
        "selp.b32 %0, 1, 0, p;\n\t}"                                              \
        : "=r"(_d) : "r"(_m), "r"(_p) : "memory");                                \
    if (!_d) {                                                                    \
        asm volatile("{\n\t.reg .pred P1;\n\t"                                    \
            "WL_%=:\n\t"                                                          \
            "mbarrier.try_wait.parity.acquire.cta.shared::cta.b64 P1, [%0], %1, 0x989680;\n\t" \
            "@P1 bra.uni WD_%=;\n\t"                                              \
            "bra.uni WL_%=;\n\t"                                                  \
            "WD_%=:\n\t}" :: "r"(_m), "r"(_p) : "memory");                        \
    } } while (0)

// ---------------- setup kernels ----------------------------------------------
__global__ void build_table() {
    int i = blockIdx.x * 256 + threadIdx.x;
    g_tab[i] = (float)cos(6.283185307179586476925286766559 * (double)i / 8192.0);
}

__global__ void convert_inputs(const float2* __restrict__ x2, const float2* __restrict__ k2) {
    size_t i = (size_t)blockIdx.x * 256 + threadIdx.x;
    const size_t XN2 = (size_t)BH * LSEQ / 2;
    float2 v = (i < XN2) ? x2[i] : k2[i - XN2];
    ((__half2*)g_A)[i] = __floats2half2_rn(v.x, v.y);
}

// Wf[n][k] (K-major [N1,K1]): n=2f -> cos(2pi f k/8192); n=2f+1 -> -sin = tab[m+2048]
__global__ void fill_Wf() {
    int idx = blockIdx.x * 256 + threadIdx.x;   // over N1*K1/2
    int n = idx >> 11, kp = idx & 2047;
    int f = n >> 1, k = kp * 2;
    int m  = (f * k) & (NFFT - 1);
    int m2 = (m + f) & (NFFT - 1);
    int add = (n & 1) ? 2048 : 0;
    __half a = __float2half_rn(g_tab[(m  + add) & (NFFT - 1)]);
    __half b = __float2half_rn(g_tab[(m2 + add) & (NFFT - 1)]);
    ((__half2*)g_Wf)[idx] = __halves2half2(a, b);
}

// Wi[n][k] (K-major [N2,K2]): k=2f -> cos(2pi f n/8192); k=2f+1 -> +sin = tab[m+6144]
__global__ void fill_Wi() {
    int idx = blockIdx.x * 256 + threadIdx.x;   // over N2*K2/2
    int n = idx >> 9, f = idx & 511;
    int m = (f * n) & (NFFT - 1);
    __half c = __float2half_rn(g_tab[m]);
    __half s = __float2half_rn(g_tab[(m + 6144) & (NFFT - 1)]);
    ((__half2*)g_Wi)[idx] = __halves2half2(c, s);
}

// Z = alpha * X * K, stored as (Zr, -Zi) fp16; alpha=2/8192 (1/8192 at f=0)
__global__ void pointwise_mul() {
    int idx = blockIdx.x * 256 + threadIdx.x;   // over BH*NBINS
    int r = idx >> 9, f = idx & 511;
    int h = r % HDIM;
    float2 X = ((const float2*)g_X)[(size_t)r * NBINS + f];
    float2 K = ((const float2*)g_X)[(size_t)(BH + h) * NBINS + f];
    float alpha = (f == 0) ? (1.0f / 8192.0f) : (2.0f / 8192.0f);
    float Zr = alpha * (X.x * K.x - X.y * K.y);
    float Zi = alpha * (X.x * K.y + X.y * K.x);
    ((__half2*)g_Z)[(size_t)r * NBINS + f] = __floats2half2_rn(Zr, -Zi);
}

// ================= tcgen05 path (sm_103a only) ================================
constexpr int BM = 128, BN = 256, BK = 64, STG = 4;
constexpr int ATILE_B  = BM * BK * 2;                  // 16384
constexpr int BTILE_B  = BN * BK * 2;                  // 32768
constexpr int STAGE_B  = ATILE_B + BTILE_B;            // 49152
constexpr int SMEM_DYN = 1024 + 1024 + STG * STAGE_B;  // slack + header + stages

#if HAS_TCGEN05
// SW128 K-major smem descriptor (Blackwell): LBO=1, SBO=64, version=1, layout=2
static constexpr uint64_t SMEM_DESC_BASE_SW128 =
    (uint64_t(2) << 61) | (uint64_t(1) << 46) | (uint64_t(64) << 32) | (uint64_t(1) << 16);
#define MAKE_SMEM_DESC(addr) (SMEM_DESC_BASE_SW128 | ((uint64_t)((addr) >> 4) & 0x3FFF))

#define TCGEN05_ALLOC(smem_addr, ncols) \
    asm volatile("tcgen05.alloc.cta_group::1.sync.aligned.shared::cta.b32 [%0], %1;" \
                 :: "r"((uint32_t)(smem_addr)), "r"((uint32_t)(ncols)) : "memory")
#define TCGEN05_DEALLOC(tmem, ncols) \
    asm volatile("tcgen05.dealloc.cta_group::1.sync.aligned.b32 %0, %1;" :: "r"(tmem), "r"((uint32_t)(ncols)))
#define TCGEN05_RELINQ() \
    asm volatile("tcgen05.relinquish_alloc_permit.cta_group::1.sync.aligned;")
#define TCGEN05_COMMIT(mbar) \
    asm volatile("tcgen05.commit.cta_group::1.mbarrier::arrive::one.shared::cluster.b64 [%0];" \
                 :: "r"((uint32_t)(mbar)) : "memory")
#define TCGEN05_FENCE_AFTER() asm volatile("tcgen05.fence::after_thread_sync;" ::: "memory")
#define TCGEN05_WAIT_LD()     asm volatile("tcgen05.wait::ld.sync.aligned;" ::: "memory")
#define TCGEN05_LD_X32(r, addr) \
    asm volatile("tcgen05.ld.sync.aligned.32x32b.x32.b32 "                         \
        "{%0, %1, %2, %3, %4, %5, %6, %7, %8, %9, %10, %11, %12, %13, %14, %15, "  \
        " %16, %17, %18, %19, %20, %21, %22, %23, %24, %25, %26, %27, %28, %29, %30, %31}, [%32];" \
        : "=r"((r)[0]),  "=r"((r)[1]),  "=r"((r)[2]),  "=r"((r)[3]),               \
          "=r"((r)[4]),  "=r"((r)[5]),  "=r"((r)[6]),  "=r"((r)[7]),               \
          "=r"((r)[8]),  "=r"((r)[9]),  "=r"((r)[10]), "=r"((r)[11]),              \
          "=r"((r)[12]), "=r"((r)[13]), "=r"((r)[14]), "=r"((r)[15]),              \
          "=r"((r)[16]), "=r"((r)[17]), "=r"((r)[18]), "=r"((r)[19]),              \
          "=r"((r)[20]), "=r"((r)[21]), "=r"((r)[22]), "=r"((r)[23]),              \
          "=r"((r)[24]), "=r"((r)[25]), "=r"((r)[26]), "=r"((r)[27]),              \
          "=r"((r)[28]), "=r"((r)[29]), "=r"((r)[30]), "=r"((r)[31])               \
        : "r"(addr))

__device__ __forceinline__ void mma_f16_ss(uint32_t d, uint64_t ad, uint64_t bd,
                                           uint32_t idesc, uint32_t enable) {
    asm volatile(
        "{\n\t.reg .pred p;\n\t"
        "setp.ne.u32 p, %4, 0;\n\t"
        "tcgen05.mma.cta_group::1.kind::f16 [%0], %1, %2, %3, {%5, %5, %5, %5}, p;\n\t}"
        :: "r"(d), "l"(ad), "l"(bd), "r"(idesc), "r"(enable), "r"(0u)
        : "memory");
}
#endif // HAS_TCGEN05

// C[M,N] = A[M,K] @ B[N,K]^T  (tcgen05; stub body if features missing)
template <int MM, int NN, int KK, int WHICH>
__global__ void __launch_bounds__(256, 1) gemm_tc(float* __restrict__ outp) {
#if HAS_TCGEN05
    extern __shared__ char smem[];
    const __half* __restrict__ A = (WHICH == 1) ? g_A  : g_Z;
    const __half* __restrict__ B = (WHICH == 1) ? g_Wf : g_Wi;
    float* __restrict__ C        = (WHICH == 1) ? g_X  : outp;

    const uint32_t sb = (smem_u32(smem) + 1023u) & ~1023u;
    const uint32_t mb_full  = sb + 8;
    const uint32_t mb_empty = sb + 40;
    const uint32_t mb_done  = sb + 72;
    const uint32_t tb = sb + 1024;

    const int tid = threadIdx.x, wid = tid >> 5, lane = tid & 31;
    const int bm = blockIdx.y * BM, bn = blockIdx.x * BN;
    constexpr int KT = KK / BK;

    if (tid == 0) {
        for (int s = 0; s < STG; s++) {
            MBARRIER_INIT(mb_full + 8 * s, 4);
            MBARRIER_INIT(mb_empty + 8 * s, 1);
        }
        MBARRIER_INIT(mb_done, 1);
    }
    if (wid == 4) { TCGEN05_ALLOC(sb, BN); TCGEN05_RELINQ(); }
    __syncthreads();
    uint32_t tmem;
    asm volatile("ld.shared.b32 %0, [%1];" : "=r"(tmem) : "r"(sb));

    if (wid < 4) {
        // producers
        for (int kt = 0; kt < KT; kt++) {
            const int s = kt & 3;
            const uint32_t ph_e = ((kt >> 2) + 1) & 1;
            MBARRIER_WAIT_PARITY(mb_empty + 8 * s, ph_e);
            const int k0 = kt * BK;
            const uint32_t sA = tb + s * STAGE_B;
            const uint32_t sBt = sA + ATILE_B;
#pragma unroll
            for (int i = 0; i < 8; i++) {
                int ci = tid + i * 128;
                int r = ci >> 3, ch = ci & 7;
                cp16(sA + SWZ(r * 128 + ch * 16), A + (size_t)(bm + r) * KK + k0 + ch * 8);
            }
#pragma unroll
            for (int i = 0; i < 16; i++) {
                int ci = tid + i * 128;
                int r = ci >> 3, ch = ci & 7;
                cp16(sBt + SWZ(r * 128 + ch * 16), B + (size_t)(bn + r) * KK + k0 + ch * 8);
            }
            cp_commit();
            if (kt >= 1) {
                cp_wait<1>();
                asm volatile("fence.proxy.async.shared::cta;" ::: "memory");
                if (lane == 0) MBARRIER_ARRIVE(mb_full + 8 * ((kt - 1) & 3));
            }
        }
        cp_wait<0>();
        asm volatile("fence.proxy.async.shared::cta;" ::: "memory");
        if (lane == 0) MBARRIER_ARRIVE(mb_full + 8 * ((KT - 1) & 3));
    } else {
        if (tid == 128) {
            const uint32_t idesc = (1u << 4) | ((BN / 8) << 17) | ((BM / 16) << 24);
            for (int kt = 0; kt < KT; kt++) {
                const int s = kt & 3;
                const uint32_t ph = (kt >> 2) & 1;
                MBARRIER_WAIT_PARITY(mb_full + 8 * s, ph);
                const uint64_t ad = MAKE_SMEM_DESC(tb + s * STAGE_B);
                const uint64_t bd = MAKE_SMEM_DESC(tb + s * STAGE_B + ATILE_B);
#pragma unroll
                for (int j = 0; j < 4; j++)
                    mma_f16_ss(tmem, ad + 2 * j, bd + 2 * j, idesc, (uint32_t)((kt | j) != 0));
                TCGEN05_COMMIT(mb_empty + 8 * s);
            }
            TCGEN05_COMMIT(mb_done);
        }
        // epilogue: warps 4-7
        MBARRIER_WAIT_PARITY(mb_done, 0);
        __syncwarp();
        TCGEN05_FENCE_AFTER();
        const int rowl = (wid & 3) * 32 + lane;
        float* crow = C + (size_t)(bm + rowl) * NN + bn;
#pragma unroll
        for (int c0 = 0; c0 < BN; c0 += 32) {
            uint32_t r[32];
            TCGEN05_LD_X32(r, tmem + c0);
            TCGEN05_WAIT_LD();
#pragma unroll
            for (int q = 0; q < 8; q++) {
                float4 v = make_float4(__uint_as_float(r[4 * q + 0]), __uint_as_float(r[4 * q + 1]),
                                       __uint_as_float(r[4 * q + 2]), __uint_as_float(r[4 * q + 3]));
                *(float4*)(crow + c0 + 4 * q) = v;
            }
        }
    }

    __syncthreads();
    if (wid == 4) TCGEN05_DEALLOC(tmem, BN);
#endif // HAS_TCGEN05
}

// ================= HMMA fallback (compiles everywhere) ========================
__device__ __forceinline__ void ldsm4(uint32_t& r0, uint32_t& r1, uint32_t& r2, uint32_t& r3, uint32_t a) {
    asm volatile("ldmatrix.sync.aligned.m8n8.x4.shared.b16 {%0,%1,%2,%3}, [%4];\n"
                 : "=r"(r0), "=r"(r1), "=r"(r2), "=r"(r3) : "r"(a));
}
__device__ __forceinline__ void mma16816(float* c, uint32_t a0, uint32_t a1, uint32_t a2, uint32_t a3,
                                         uint32_t b0, uint32_t b1) {
    asm volatile(
        "mma.sync.aligned.m16n8k16.row.col.f32.f16.f16.f32 "
        "{%0,%1,%2,%3}, {%4,%5,%6,%7}, {%8,%9}, {%0,%1,%2,%3};\n"
        : "+f"(c[0]), "+f"(c[1]), "+f"(c[2]), "+f"(c[3])
        : "r"(a0), "r"(a1), "r"(a2), "r"(a3), "r"(b0), "r"(b1));
}

// C[M,N] = A[M,K] @ B[N,K]^T  (both operands K-major), 128x128x32 tiles.
template <int MM, int NN, int KK, int WHICH>
__global__ void __launch_bounds__(256, 2) gemm_hmma(float* __restrict__ outp) {
    const __half* __restrict__ A = (WHICH == 1) ? g_A  : g_Z;
    const __half* __restrict__ B = (WHICH == 1) ? g_Wf : g_Wi;
    float* __restrict__ C        = (WHICH == 1) ? g_X  : outp;

    constexpr int FBM = 128, FBN = 128, FBK = 32;
    constexpr int LDT = FBK + 8;   // 40 halves -> 80B rows, conflict-free
    __shared__ __align__(16) __half As[2][FBM * LDT];
    __shared__ __align__(16) __half Bs[2][FBN * LDT];

    const int tid = threadIdx.x, lane = tid & 31, wid = tid >> 5;
    const int wm = wid & 3, wn = wid >> 2;
    const int bm = blockIdx.y * FBM, bn = blockIdx.x * FBN;

    float acc[2][8][4];
#pragma unroll
    for (int i = 0; i < 2; i++)
#pragma unroll
        for (int j = 0; j < 8; j++)
#pragma unroll
            for (int q = 0; q < 4; q++) acc[i][j][q] = 0.f;

    const int trow = tid >> 2, tcol = (tid & 3) << 3;

    auto load_tile = [&](int kt, int buf) {
        const int k0 = kt * FBK;
        const __half* ag = A + (size_t)(bm + trow) * KK + k0 + tcol;
        cp16(smem_u32(&As[buf][trow * LDT + tcol]), ag);
        cp16(smem_u32(&As[buf][(trow + 64) * LDT + tcol]), ag + (size_t)64 * KK);
        const __half* bg = B + (size_t)(bn + trow) * KK + k0 + tcol;
        cp16(smem_u32(&Bs[buf][trow * LDT + tcol]), bg);
        cp16(smem_u32(&Bs[buf][(trow + 64) * LDT + tcol]), bg + (size_t)64 * KK);
        cp_commit();
    };

    load_tile(0, 0);

    constexpr int KT = KK / FBK;
    for (int kt = 0; kt < KT; kt++) {
        const int buf = kt & 1;
        if (kt + 1 < KT) { load_tile(kt + 1, buf ^ 1); cp_wait<1>(); }
        else            { cp_wait<0>(); }
        __syncthreads();

#pragma unroll
        for (int ks = 0; ks < 2; ks++) {
            uint32_t a[2][4], b[4][4];
#pragma unroll
            for (int mt = 0; mt < 2; mt++) {
                int r = wm * 32 + mt * 16 + (lane & 15);
                int c = ks * 16 + ((lane >> 4) << 3);
                ldsm4(a[mt][0], a[mt][1], a[mt][2], a[mt][3], smem_u32(&As[buf][r * LDT + c]));
            }
#pragma unroll
            for (int nt = 0; nt < 4; nt++) {
                int r = wn * 64 + nt * 16 + (lane & 15);
                int c = ks * 16 + ((lane >> 4) << 3);
                ldsm4(b[nt][0], b[nt][1], b[nt][2], b[nt][3], smem_u32(&Bs[buf][r * LDT + c]));
            }
#pragma unroll
            for (int mt = 0; mt < 2; mt++)
#pragma unroll
                for (int nt = 0; nt < 8; nt++)
                    // n8 sub-tile j of pair: regs (r[j], r[j+2]) = (k0-7, k8-15)
                    mma16816(acc[mt][nt], a[mt][0], a[mt][1], a[mt][2], a[mt][3],
                             b[nt >> 1][nt & 1], b[nt >> 1][(nt & 1) + 2]);
        }
        __syncthreads();
    }

#pragma unroll
    for (int mt = 0; mt < 2; mt++) {
#pragma unroll
        for (int nt = 0; nt < 8; nt++) {
            int row = bm + wm * 32 + mt * 16 + (lane >> 2);
            int col = bn + wn * 64 + nt * 8 + ((lane & 3) << 1);
            C[(size_t)row * NN + col]           = acc[mt][nt][0];
            C[(size_t)row * NN + col + 1]       = acc[mt][nt][1];
            C[(size_t)(row + 8) * NN + col]     = acc[mt][nt][2];
            C[(size_t)(row + 8) * NN + col + 1] = acc[mt][nt][3];
        }
    }
}

// ---------------- launch -------------------------------------------------------
extern "C" void kernel_launch(void* const* d_in, const int* in_sizes, int n_in,
                              void* d_out, int out_size) {
    const float2* x2 = (const float2*)d_in[0];
    const float2* k2 = (const float2*)d_in[1];
    float* out = (float*)d_out;

    // Detect whether the loaded image for this device has the real tcgen05 body.
    cudaFuncAttributes fa{};
    bool use_tc = (cudaFuncGetAttributes(&fa, (const void*)gemm_tc<M1, N1, K1, 1>) == cudaSuccess)
                  && (fa.numRegs >= 40);

    build_table<<<NFFT / 256, 256>>>();
    convert_inputs<<<(M1 * K1 / 2) / 256, 256>>>(x2, k2);
    fill_Wf<<<(N1 * K1 / 2) / 256, 256>>>();
    fill_Wi<<<(N2 * K2 / 2) / 256, 256>>>();

    if (use_tc) {
        cudaFuncSetAttribute((const void*)gemm_tc<M1, N1, K1, 1>,
                             cudaFuncAttributeMaxDynamicSharedMemorySize, SMEM_DYN);
        cudaFuncSetAttribute((const void*)gemm_tc<M2, N2, K2, 2>,
                             cudaFuncAttributeMaxDynamicSharedMemorySize, SMEM_DYN);
        gemm_tc<M1, N1, K1, 1><<<dim3(N1 / BN, M1 / BM), 256, SMEM_DYN>>>(nullptr);
        pointwise_mul<<<(BH * NBINS) / 256, 256>>>();
        gemm_tc<M2, N2, K2, 2><<<dim3(N2 / BN, M2 / BM), 256, SMEM_DYN>>>(out);
    } else {
        gemm_hmma<M1, N1, K1, 1><<<dim3(N1 / 128, M1 / 128), 256>>>(nullptr);
        pointwise_mul<<<(BH * NBINS) / 256, 256>>>();
        gemm_hmma<M2, N2, K2, 2><<<dim3(N2 / 128, M2 / 128), 256>>>(out);
    }
}

// round 4
// speedup vs baseline: 2.5765x; 1.2474x over previous
#include <cuda_runtime.h>
#include <cuda_fp16.h>
#include <math.h>
#include <stdint.h>

// ---------------- problem constants -----------------------------------------
#define LSEQ  4096
#define NFFT  8192
#define NBINS 512
#define BH    6144         // B*H
#define HDIM  768
#define M1    6912         // BH + HDIM (k rows ride along in GEMM1)
#define K1    4096
#define N1    1024         // 512 bins x (re, im)
#define M2    6144
#define K2    1024
#define N2    4096

// sm_103a feature pass? (tcgen05/TMEM only exist in arch-specific compile)
#if defined(__CUDA_ARCH__) && (__CUDA_ARCH__ >= 1000) && \
    (defined(__CUDA_ARCH_FEAT_SM103_ALL) || defined(__CUDA_ARCH_SPECIFIC__) || \
     defined(__CUDA_ARCH_FAMILY_SPECIFIC__))
#define HAS_TCGEN05 1
#else
#define HAS_TCGEN05 0
#endif

// ---------------- device scratch (no allocs allowed) ------------------------
__device__ __align__(16) __half g_A [(size_t)M1 * K1];   // fallback only
__device__ __align__(16) __half g_Wf[(size_t)N1 * K1];   // [N1,K1] fwd DFT weights (K-major)
__device__ __align__(16) float  g_X [(size_t)M1 * N1];   // spectra
__device__ __align__(16) __half g_Z [(size_t)M2 * K2];   // scaled product spectrum
__device__ __align__(16) __half g_Wi[(size_t)N2 * K2];   // [N2,K2] inv DFT weights (K-major)

// ---------------- generic PTX helpers ----------------------------------------
__device__ __forceinline__ uint32_t smem_u32(const void* p) {
    return (uint32_t)__cvta_generic_to_shared(p);
}
__device__ __forceinline__ void cp16(uint32_t dst, const void* src) {
    asm volatile("cp.async.cg.shared.global [%0], [%1], 16;\n" :: "r"(dst), "l"(src));
}
__device__ __forceinline__ void cp_commit() {
    asm volatile("cp.async.commit_group;\n" ::: "memory");
}
template <int N>
__device__ __forceinline__ void cp_wait() {
    asm volatile("cp.async.wait_group %0;\n" :: "n"(N) : "memory");
}
__device__ __forceinline__ uint32_t cluster_rank() {
    uint32_t r; asm("mov.u32 %0, %%cluster_ctarank;" : "=r"(r)); return r;
}
#define SWZ(off) ((off) ^ (((off) >> 3) & 0x70))

#define MBARRIER_INIT(mbar, count) \
    asm volatile("mbarrier.init.shared.b64 [%0], %1;" :: "r"((uint32_t)(mbar)), "r"((uint32_t)(count)) : "memory")
// arrive on the LEADER CTA's barrier at the same offset (clear peer bit 24)
#define MBARRIER_ARRIVE_LEADER(mbar) \
    asm volatile("{\n\t.reg .b32 la;\n\t" \
        "and.b32 la, %0, 0xFEFFFFFF;\n\t" \
        "mbarrier.arrive.shared::cluster.b64 _, [la];\n\t}" \
        :: "r"((uint32_t)(mbar)) : "memory")
#define MBARRIER_WAIT_PARITY(mbar, parity) do {                                   \
    uint32_t _m = (uint32_t)(mbar); uint32_t _p = (uint32_t)(parity); uint32_t _d; \
    asm volatile("{\n\t.reg .pred p;\n\t"                                         \
        "mbarrier.try_wait.parity.acquire.cta.shared::cta.b64 p, [%1], %2;\n\t"   \
        "selp.b32 %0, 1, 0, p;\n\t}"                                              \
        : "=r"(_d) : "r"(_m), "r"(_p) : "memory");                                \
    if (!_d) {                                                                    \
        asm volatile("{\n\t.reg .pred P1;\n\t"                                    \
            "WL_%=:\n\t"                                                          \
            "mbarrier.try_wait.parity.acquire.cta.shared::cta.b64 P1, [%0], %1, 0x989680;\n\t" \
            "@P1 bra.uni WD_%=;\n\t"                                              \
            "bra.uni WL_%=;\n\t"                                                  \
            "WD_%=:\n\t}" :: "r"(_m), "r"(_p) : "memory");                        \
    } } while (0)
#define CLUSTER_SYNC() do { \
    asm volatile("barrier.cluster.arrive.aligned;" ::: "memory"); \
    asm volatile("barrier.cluster.wait.aligned;" ::: "memory"); } while (0)

// ---------------- setup kernels ----------------------------------------------
#define TWO_PI_OVER_N 7.6699039e-4f   // 2*pi/8192

// fallback only: A = [x;k] fp16
__global__ void convert_inputs(const float2* __restrict__ x2, const float2* __restrict__ k2) {
    size_t i = (size_t)blockIdx.x * 256 + threadIdx.x;
    const size_t XN2 = (size_t)BH * LSEQ / 2;
    float2 v = (i < XN2) ? x2[i] : k2[i - XN2];
    ((__half2*)g_A)[i] = __floats2half2_rn(v.x, v.y);
}

// Wf[n][k] (K-major [N1,K1]): n=2f -> cos(2pi f k/8192); n=2f+1 -> -sin
__global__ void fill_Wf() {
    int idx = blockIdx.x * 256 + threadIdx.x;   // N1*K1/8 threads
    int n = idx >> 9, c = (idx & 511) << 3;
    int f = n >> 1, odd = n & 1;
    __half h[8];
#pragma unroll
    for (int j = 0; j < 8; j++) {
        int m = (f * (c + j)) & (NFFT - 1);
        float sv, cv;
        __sincosf((float)m * TWO_PI_OVER_N, &sv, &cv);
        h[j] = __float2half_rn(odd ? -sv : cv);
    }
    *(uint4*)(g_Wf + (size_t)n * K1 + c) = *(uint4*)h;
}

// Wi[n][k] (K-major [N2,K2]): k=2f -> cos(2pi f n/8192); k=2f+1 -> +sin
__global__ void fill_Wi() {
    int idx = blockIdx.x * 256 + threadIdx.x;   // N2*K2/8 threads
    int n = idx >> 7, c = (idx & 127) << 3;
    __half h[8];
#pragma unroll
    for (int j = 0; j < 4; j++) {
        int f = (c >> 1) + j;
        int m = (f * n) & (NFFT - 1);
        float sv, cv;
        __sincosf((float)m * TWO_PI_OVER_N, &sv, &cv);
        h[2 * j]     = __float2half_rn(cv);
        h[2 * j + 1] = __float2half_rn(sv);
    }
    *(uint4*)(g_Wi + (size_t)n * K2 + c) = *(uint4*)h;
}

// Z = alpha * X * K, stored as (Zr, -Zi) fp16; alpha=2/8192 (1/8192 at f=0)
__global__ void pointwise_mul() {
    int idx = blockIdx.x * 256 + threadIdx.x;   // BH*NBINS threads
    int r = idx >> 9, f = idx & 511;
    int h = r % HDIM;
    float2 X = ((const float2*)g_X)[(size_t)r * NBINS + f];
    float2 K = ((const float2*)g_X)[(size_t)(BH + h) * NBINS + f];
    float alpha = (f == 0) ? (1.0f / 8192.0f) : (2.0f / 8192.0f);
    float Zr = alpha * (X.x * K.x - X.y * K.y);
    float Zi = alpha * (X.x * K.y + X.y * K.x);
    ((__half2*)g_Z)[(size_t)r * NBINS + f] = __floats2half2_rn(Zr, -Zi);
}

// ================= tcgen05 cg2 path (sm_103a only) ============================
// C[M,N] = A[M,K] @ B[N,K]^T.  Cluster(2,1,1): M-tile 256 (128 rows/CTA),
// N-tile 512 via two N=256 cg2 MMAs (D cols 0 / 256), BK=64, 4-stage cp.async.
constexpr int STG = 4;
constexpr int ATILE_B  = 128 * 64 * 2;                 // 16 KB
constexpr int BTILE_B  = 256 * 64 * 2;                 // 32 KB (this CTA's B half rows)
constexpr int STAGE_B  = ATILE_B + BTILE_B;            // 48 KB
constexpr int SMEM_DYN = 1024 + 1024 + STG * STAGE_B;  // 194 KB

#if HAS_TCGEN05
static constexpr uint64_t SMEM_DESC_BASE_SW128 =
    (uint64_t(2) << 61) | (uint64_t(1) << 46) | (uint64_t(64) << 32) | (uint64_t(1) << 16);
#define MAKE_SMEM_DESC(addr) (SMEM_DESC_BASE_SW128 | ((uint64_t)((addr) >> 4) & 0x3FFF))

#define TCGEN05_ALLOC_CG2(smem_addr, ncols) \
    asm volatile("tcgen05.alloc.cta_group::2.sync.aligned.shared::cta.b32 [%0], %1;" \
                 :: "r"((uint32_t)(smem_addr)), "r"((uint32_t)(ncols)) : "memory")
#define TCGEN05_DEALLOC_CG2(tmem, ncols) \
    asm volatile("tcgen05.dealloc.cta_group::2.sync.aligned.b32 %0, %1;" :: "r"(tmem), "r"((uint32_t)(ncols)))
#define TCGEN05_RELINQ_CG2() \
    asm volatile("tcgen05.relinquish_alloc_permit.cta_group::2.sync.aligned;")
#define TCGEN05_COMMIT_MC_CG2(mbar, mask) \
    asm volatile("tcgen05.commit.cta_group::2.mbarrier::arrive::one.shared::cluster.multicast::cluster.b64 [%0], %1;" \
                 :: "r"((uint32_t)(mbar)), "h"((uint16_t)(mask)) : "memory")
#define TCGEN05_FENCE_AFTER() asm volatile("tcgen05.fence::after_thread_sync;" ::: "memory")
#define TCGEN05_WAIT_LD()     asm volatile("tcgen05.wait::ld.sync.aligned;" ::: "memory")
#define TCGEN05_LD_X32(r, addr) \
    asm volatile("tcgen05.ld.sync.aligned.32x32b.x32.b32 "                         \
        "{%0, %1, %2, %3, %4, %5, %6, %7, %8, %9, %10, %11, %12, %13, %14, %15, "  \
        " %16, %17, %18, %19, %20, %21, %22, %23, %24, %25, %26, %27, %28, %29, %30, %31}, [%32];" \
        : "=r"((r)[0]),  "=r"((r)[1]),  "=r"((r)[2]),  "=r"((r)[3]),               \
          "=r"((r)[4]),  "=r"((r)[5]),  "=r"((r)[6]),  "=r"((r)[7]),               \
          "=r"((r)[8]),  "=r"((r)[9]),  "=r"((r)[10]), "=r"((r)[11]),              \
          "=r"((r)[12]), "=r"((r)[13]), "=r"((r)[14]), "=r"((r)[15]),              \
          "=r"((r)[16]), "=r"((r)[17]), "=r"((r)[18]), "=r"((r)[19]),              \
          "=r"((r)[20]), "=r"((r)[21]), "=r"((r)[22]), "=r"((r)[23]),              \
          "=r"((r)[24]), "=r"((r)[25]), "=r"((r)[26]), "=r"((r)[27]),              \
          "=r"((r)[28]), "=r"((r)[29]), "=r"((r)[30]), "=r"((r)[31])               \
        : "r"(addr))

// cg2 f16 SS MMA: fp16 x fp16 -> fp32, M=256 across pair, N=256
__device__ __forceinline__ void mma_f16_ss_cg2(uint32_t d, uint64_t ad, uint64_t bd,
                                               uint32_t idesc, uint32_t enable) {
    asm volatile(
        "{\n\t.reg .pred p;\n\t"
        "setp.ne.u32 p, %4, 0;\n\t"
        "tcgen05.mma.cta_group::2.kind::f16 [%0], %1, %2, %3, "
        "{%5, %5, %5, %5, %5, %5, %5, %5}, p;\n\t}"
        :: "r"(d), "l"(ad), "l"(bd), "r"(idesc), "r"(enable), "r"(0u)
        : "memory");
}
#endif // HAS_TCGEN05

// WHICH=1: A = [x;k] fp32 (converted in producer), B=g_Wf, C=g_X,  NN=1024, KK=4096
// WHICH=2: A = g_Z fp16 (cp.async),               B=g_Wi, C=outp, NN=4096, KK=1024
template <int KK, int WHICH>
__global__ void __launch_bounds__(256, 1) __cluster_dims__(2, 1, 1)
gemm_tc2(const float* __restrict__ xin, const float* __restrict__ kin, float* __restrict__ outp) {
#if HAS_TCGEN05
    extern __shared__ char smem[];
    constexpr int NN = (WHICH == 1) ? N1 : N2;
    constexpr int KT = KK / 64;
    const __half* __restrict__ Bsrc = (WHICH == 1) ? g_Wf : g_Wi;
    float* __restrict__ C            = (WHICH == 1) ? g_X  : outp;

    const uint32_t sb = (smem_u32(smem) + 1023u) & ~1023u;
    const uint32_t mb_full  = sb + 8;    // 4 x 8B (leader's are the live ones)
    const uint32_t mb_empty = sb + 40;   // 4 x 8B (per-CTA, multicast target)
    const uint32_t mb_done  = sb + 72;
    const uint32_t tb = sb + 1024;

    const int tid = threadIdx.x, wid = tid >> 5, lane = tid & 31;
    const uint32_t rank = cluster_rank();
    const int bn = blockIdx.x >> 1;
    const int mbase = blockIdx.y * 256 + (int)rank * 128;   // this CTA's 128 A rows

    if (tid == 0) {
        for (int s = 0; s < STG; s++) {
            MBARRIER_INIT(mb_full + 8 * s, 8);   // 4 producer warps x 2 CTAs
            MBARRIER_INIT(mb_empty + 8 * s, 1);  // one multicast commit
        }
        MBARRIER_INIT(mb_done, 1);
    }
    if (wid == 4) { TCGEN05_ALLOC_CG2(sb, 512); TCGEN05_RELINQ_CG2(); }
    __syncthreads();
    uint32_t tmem;
    asm volatile("ld.shared.b32 %0, [%1];" : "=r"(tmem) : "r"(sb));
    CLUSTER_SYNC();   // peer mbarriers + TMEM alloc visible before any cluster traffic

    if (wid < 4) {
        // ------------------------------ producers ----------------------------
        for (int kt = 0; kt < KT; kt++) {
            const int s = kt & 3;
            MBARRIER_WAIT_PARITY(mb_empty + 8 * s, ((kt >> 2) + 1) & 1);
            const int k0 = kt * 64;
            const uint32_t sA = tb + s * STAGE_B;
            const uint32_t sB = sA + ATILE_B;

            if (WHICH == 1) {
                // A: fp32 -> fp16 inline (rows are uniformly x or k per CTA-tile)
                const float* src = (mbase < BH) ? xin + (size_t)mbase * K1
                                                : kin + (size_t)(mbase - BH) * K1;
#pragma unroll
                for (int i = 0; i < 8; i++) {
                    int ci = tid + i * 128;
                    int r = ci >> 3, c8 = ci & 7;
                    const float4* p = (const float4*)(src + (size_t)r * K1 + k0 + c8 * 8);
                    float4 v0 = p[0], v1 = p[1];
                    __half2 a0 = __floats2half2_rn(v0.x, v0.y);
                    __half2 a1 = __floats2half2_rn(v0.z, v0.w);
                    __half2 a2 = __floats2half2_rn(v1.x, v1.y);
                    __half2 a3 = __floats2half2_rn(v1.z, v1.w);
                    asm volatile("st.shared.v4.b32 [%0], {%1,%2,%3,%4};"
                        :: "r"(sA + SWZ(r * 128 + c8 * 16)),
                           "r"(*(uint32_t*)&a0), "r"(*(uint32_t*)&a1),
                           "r"(*(uint32_t*)&a2), "r"(*(uint32_t*)&a3) : "memory");
                }
            } else {
                const __half* Az = g_Z + (size_t)mbase * KK + k0;
#pragma unroll
                for (int i = 0; i < 8; i++) {
                    int ci = tid + i * 128;
                    int r = ci >> 3, c8 = ci & 7;
                    cp16(sA + SWZ(r * 128 + c8 * 16), Az + (size_t)r * KK + c8 * 8);
                }
            }
            // B: this CTA's half-rows of both N=256 groups
#pragma unroll
            for (int g = 0; g < 2; g++) {
                const __half* bg = Bsrc + (size_t)(bn * 512 + g * 256 + (int)rank * 128) * KK + k0;
#pragma unroll
                for (int i = 0; i < 8; i++) {
                    int ci = tid + i * 128;
                    int r = ci >> 3, c8 = ci & 7;
                    cp16(sB + g * 16384 + SWZ(r * 128 + c8 * 16), bg + (size_t)r * KK + c8 * 8);
                }
            }
            cp_commit();
            if (kt >= 1) {
                cp_wait<1>();
                asm volatile("fence.proxy.async.shared::cta;" ::: "memory");
                if (lane == 0) MBARRIER_ARRIVE_LEADER(mb_full + 8 * ((kt - 1) & 3));
            }
        }
        cp_wait<0>();
        asm volatile("fence.proxy.async.shared::cta;" ::: "memory");
        if (lane == 0) MBARRIER_ARRIVE_LEADER(mb_full + 8 * ((KT - 1) & 3));
    } else {
        // ------------------------------ MMA issuer ---------------------------
        if (rank == 0 && tid == 128) {
            const uint32_t idesc = (1u << 4) | (32u << 17) | (16u << 24);  // F32, N=256, M=256
            for (int kt = 0; kt < KT; kt++) {
                const int s = kt & 3;
                MBARRIER_WAIT_PARITY(mb_full + 8 * s, (kt >> 2) & 1);
                const uint64_t ad  = MAKE_SMEM_DESC(tb + s * STAGE_B);
                const uint64_t bd0 = MAKE_SMEM_DESC(tb + s * STAGE_B + ATILE_B);
                const uint64_t bd1 = bd0 + 1024;   // +16KB: second 128-row B group
#pragma unroll
                for (int j = 0; j < 4; j++) {
                    uint32_t en = (uint32_t)((kt | j) != 0);
                    mma_f16_ss_cg2(tmem,       ad + 2 * j, bd0 + 2 * j, idesc, en);
                    mma_f16_ss_cg2(tmem + 256, ad + 2 * j, bd1 + 2 * j, idesc, en);
                }
                TCGEN05_COMMIT_MC_CG2(mb_empty + 8 * s, 3);
            }
            TCGEN05_COMMIT_MC_CG2(mb_done, 3);
        }
        // ------------------------------ epilogue -----------------------------
        MBARRIER_WAIT_PARITY(mb_done, 0);
        TCGEN05_FENCE_AFTER();
        const int rowl = (wid - 4) * 32 + lane;           // 0..127 local row
        float* crow = C + (size_t)(mbase + rowl) * NN + bn * 512;
#pragma unroll
        for (int c0 = 0; c0 < 512; c0 += 32) {
            uint32_t r[32];
            TCGEN05_LD_X32(r, tmem + c0);
            TCGEN05_WAIT_LD();
#pragma unroll
            for (int q = 0; q < 8; q++) {
                float4 v = make_float4(__uint_as_float(r[4 * q + 0]), __uint_as_float(r[4 * q + 1]),
                                       __uint_as_float(r[4 * q + 2]), __uint_as_float(r[4 * q + 3]));
                *(float4*)(crow + c0 + 4 * q) = v;
            }
        }
    }

    __syncthreads();
    if (wid == 4) TCGEN05_DEALLOC_CG2(tmem, 512);
    CLUSTER_SYNC();
#endif // HAS_TCGEN05
}

// ================= HMMA fallback (compiles everywhere) ========================
__device__ __forceinline__ void ldsm4(uint32_t& r0, uint32_t& r1, uint32_t& r2, uint32_t& r3, uint32_t a) {
    asm volatile("ldmatrix.sync.aligned.m8n8.x4.shared.b16 {%0,%1,%2,%3}, [%4];\n"
                 : "=r"(r0), "=r"(r1), "=r"(r2), "=r"(r3) : "r"(a));
}
__device__ __forceinline__ void mma16816(float* c, uint32_t a0, uint32_t a1, uint32_t a2, uint32_t a3,
                                         uint32_t b0, uint32_t b1) {
    asm volatile(
        "mma.sync.aligned.m16n8k16.row.col.f32.f16.f16.f32 "
        "{%0,%1,%2,%3}, {%4,%5,%6,%7}, {%8,%9}, {%0,%1,%2,%3};\n"
        : "+f"(c[0]), "+f"(c[1]), "+f"(c[2]), "+f"(c[3])
        : "r"(a0), "r"(a1), "r"(a2), "r"(a3), "r"(b0), "r"(b1));
}

template <int MM, int NN, int KK, int WHICH>
__global__ void __launch_bounds__(256, 2) gemm_hmma(float* __restrict__ outp) {
    const __half* __restrict__ A = (WHICH == 1) ? g_A  : g_Z;
    const __half* __restrict__ B = (WHICH == 1) ? g_Wf : g_Wi;
    float* __restrict__ C        = (WHICH == 1) ? g_X  : outp;

    constexpr int FBM = 128, FBN = 128, FBK = 32;
    constexpr int LDT = FBK + 8;
    __shared__ __align__(16) __half As[2][FBM * LDT];
    __shared__ __align__(16) __half Bs[2][FBN * LDT];

    const int tid = threadIdx.x, lane = tid & 31, wid = tid >> 5;
    const int wm = wid & 3, wn = wid >> 2;
    const int bm = blockIdx.y * FBM, bn = blockIdx.x * FBN;

    float acc[2][8][4];
#pragma unroll
    for (int i = 0; i < 2; i++)
#pragma unroll
        for (int j = 0; j < 8; j++)
#pragma unroll
            for (int q = 0; q < 4; q++) acc[i][j][q] = 0.f;

    const int trow = tid >> 2, tcol = (tid & 3) << 3;
    auto load_tile = [&](int kt, int buf) {
        const int k0 = kt * FBK;
        const __half* ag = A + (size_t)(bm + trow) * KK + k0 + tcol;
        cp16(smem_u32(&As[buf][trow * LDT + tcol]), ag);
        cp16(smem_u32(&As[buf][(trow + 64) * LDT + tcol]), ag + (size_t)64 * KK);
        const __half* bg = B + (size_t)(bn + trow) * KK + k0 + tcol;
        cp16(smem_u32(&Bs[buf][trow * LDT + tcol]), bg);
        cp16(smem_u32(&Bs[buf][(trow + 64) * LDT + tcol]), bg + (size_t)64 * KK);
        cp_commit();
    };

    load_tile(0, 0);
    constexpr int KT = KK / FBK;
    for (int kt = 0; kt < KT; kt++) {
        const int buf = kt & 1;
        if (kt + 1 < KT) { load_tile(kt + 1, buf ^ 1); cp_wait<1>(); }
        else            { cp_wait<0>(); }
        __syncthreads();
#pragma unroll
        for (int ks = 0; ks < 2; ks++) {
            uint32_t a[2][4], b[4][4];
#pragma unroll
            for (int mt = 0; mt < 2; mt++) {
                int r = wm * 32 + mt * 16 + (lane & 15);
                int c = ks * 16 + ((lane >> 4) << 3);
                ldsm4(a[mt][0], a[mt][1], a[mt][2], a[mt][3], smem_u32(&As[buf][r * LDT + c]));
            }
#pragma unroll
            for (int nt = 0; nt < 4; nt++) {
                int r = wn * 64 + nt * 16 + (lane & 15);
                int c = ks * 16 + ((lane >> 4) << 3);
                ldsm4(b[nt][0], b[nt][1], b[nt][2], b[nt][3], smem_u32(&Bs[buf][r * LDT + c]));
            }
#pragma unroll
            for (int mt = 0; mt < 2; mt++)
#pragma unroll
                for (int nt = 0; nt < 8; nt++)
                    mma16816(acc[mt][nt], a[mt][0], a[mt][1], a[mt][2], a[mt][3],
                             b[nt >> 1][nt & 1], b[nt >> 1][(nt & 1) + 2]);
        }
        __syncthreads();
    }
#pragma unroll
    for (int mt = 0; mt < 2; mt++)
#pragma unroll
        for (int nt = 0; nt < 8; nt++) {
            int row = bm + wm * 32 + mt * 16 + (lane >> 2);
            int col = bn + wn * 64 + nt * 8 + ((lane & 3) << 1);
            C[(size_t)row * NN + col]           = acc[mt][nt][0];
            C[(size_t)row * NN + col + 1]       = acc[mt][nt][1];
            C[(size_t)(row + 8) * NN + col]     = acc[mt][nt][2];
            C[(size_t)(row + 8) * NN + col + 1] = acc[mt][nt][3];
        }
}

// ---------------- launch -------------------------------------------------------
extern "C" void kernel_launch(void* const* d_in, const int* in_sizes, int n_in,
                              void* d_out, int out_size) {
    const float* x = (const float*)d_in[0];
    const float* k = (const float*)d_in[1];
    float* out = (float*)d_out;

    cudaFuncAttributes fa{};
    bool use_tc = (cudaFuncGetAttributes(&fa, (const void*)gemm_tc2<K1, 1>) == cudaSuccess)
                  && (fa.numRegs >= 40);

    fill_Wf<<<(N1 * K1 / 8) / 256, 256>>>();
    fill_Wi<<<(N2 * K2 / 8) / 256, 256>>>();

    if (use_tc) {
        cudaFuncSetAttribute((const void*)gemm_tc2<K1, 1>,
                             cudaFuncAttributeMaxDynamicSharedMemorySize, SMEM_DYN);
        cudaFuncSetAttribute((const void*)gemm_tc2<K2, 2>,
                             cudaFuncAttributeMaxDynamicSharedMemorySize, SMEM_DYN);
        gemm_tc2<K1, 1><<<dim3(2 * N1 / 512, M1 / 256), 256, SMEM_DYN>>>(x, k, nullptr);
        pointwise_mul<<<(BH * NBINS) / 256, 256>>>();
        gemm_tc2<K2, 2><<<dim3(2 * N2 / 512, M2 / 256), 256, SMEM_DYN>>>(x, k, out);
    } else {
        convert_inputs<<<(M1 * K1 / 2) / 256, 256>>>((const float2*)x, (const float2*)k);
        gemm_hmma<M1, N1, K1, 1><<<dim3(N1 / 128, M1 / 128), 256>>>(nullptr);
        pointwise_mul<<<(BH * NBINS) / 256, 256>>>();
        gemm_hmma<M2, N2, K2, 2><<<dim3(N2 / 128, M2 / 128), 256>>>(out);
    }
}

// round 5
// speedup vs baseline: 2.6828x; 1.0412x over previous
#include <cuda_runtime.h>
#include <cuda_fp16.h>
#include <math.h>
#include <stdint.h>

// ---------------- problem constants -----------------------------------------
#define LSEQ  4096
#define NFFT  8192
#define NBINS 512
#define BH    6144         // B*H
#define HDIM  768
#define M1    6912         // BH + HDIM (k rows ride along in GEMM1)
#define K1    4096
#define N1    1024         // 512 bins x (re, im)
#define M2    6144
#define K2    1024
#define N2    4096

// sm_103a feature pass? (tcgen05/TMEM only exist in arch-specific compile)
#if defined(__CUDA_ARCH__) && (__CUDA_ARCH__ >= 1000) && \
    (defined(__CUDA_ARCH_FEAT_SM103_ALL) || defined(__CUDA_ARCH_SPECIFIC__) || \
     defined(__CUDA_ARCH_FAMILY_SPECIFIC__))
#define HAS_TCGEN05 1
#else
#define HAS_TCGEN05 0
#endif

// ---------------- device scratch (no allocs allowed) ------------------------
__device__ __align__(16) __half g_A [(size_t)M1 * K1];   // fallback only
__device__ __align__(16) __half g_Wf[(size_t)N1 * K1];   // [N1,K1] fwd DFT weights (K-major)
__device__ __align__(16) __half g_X [(size_t)M1 * N1];   // spectra, fp16
__device__ __align__(16) __half g_Z [(size_t)M2 * K2];   // scaled product spectrum
__device__ __align__(16) __half g_Wi[(size_t)N2 * K2];   // [N2,K2] inv DFT weights (K-major)

// ---------------- generic PTX helpers ----------------------------------------
__device__ __forceinline__ uint32_t smem_u32(const void* p) {
    return (uint32_t)__cvta_generic_to_shared(p);
}
__device__ __forceinline__ void cp16(uint32_t dst, const void* src) {
    asm volatile("cp.async.cg.shared.global [%0], [%1], 16;\n" :: "r"(dst), "l"(src));
}
__device__ __forceinline__ void cp_commit() {
    asm volatile("cp.async.commit_group;\n" ::: "memory");
}
template <int N>
__device__ __forceinline__ void cp_wait() {
    asm volatile("cp.async.wait_group %0;\n" :: "n"(N) : "memory");
}
__device__ __forceinline__ uint32_t cluster_rank() {
    uint32_t r; asm("mov.u32 %0, %%cluster_ctarank;" : "=r"(r)); return r;
}
#define SWZ(off) ((off) ^ (((off) >> 3) & 0x70))

#define MBARRIER_INIT(mbar, count) \
    asm volatile("mbarrier.init.shared.b64 [%0], %1;" :: "r"((uint32_t)(mbar)), "r"((uint32_t)(count)) : "memory")
#define MBARRIER_ARRIVE_LEADER(mbar) \
    asm volatile("{\n\t.reg .b32 la;\n\t" \
        "and.b32 la, %0, 0xFEFFFFFF;\n\t" \
        "mbarrier.arrive.shared::cluster.b64 _, [la];\n\t}" \
        :: "r"((uint32_t)(mbar)) : "memory")
#define MBARRIER_WAIT_PARITY(mbar, parity) do {                                   \
    uint32_t _m = (uint32_t)(mbar); uint32_t _p = (uint32_t)(parity); uint32_t _d; \
    asm volatile("{\n\t.reg .pred p;\n\t"                                         \
        "mbarrier.try_wait.parity.acquire.cta.shared::cta.b64 p, [%1], %2;\n\t"   \
        "selp.b32 %0, 1, 0, p;\n\t}"                                              \
        : "=r"(_d) : "r"(_m), "r"(_p) : "memory");                                \
    if (!_d) {                                                                    \
        asm volatile("{\n\t.reg .pred P1;\n\t"                                    \
            "WL_%=:\n\t"                                                          \
            "mbarrier.try_wait.parity.acquire.cta.shared::cta.b64 P1, [%0], %1, 0x989680;\n\t" \
            "@P1 bra.uni WD_%=;\n\t"                                              \
            "bra.uni WL_%=;\n\t"                                                  \
            "WD_%=:\n\t}" :: "r"(_m), "r"(_p) : "memory");                        \
    } } while (0)
#define CLUSTER_SYNC() do { \
    asm volatile("barrier.cluster.arrive.aligned;" ::: "memory"); \
    asm volatile("barrier.cluster.wait.aligned;" ::: "memory"); } while (0)

// ---------------- setup kernels ----------------------------------------------
#define TWO_PI_OVER_N 7.6699039e-4f   // 2*pi/8192

// fallback only: A = [x;k] fp16
__global__ void convert_inputs(const float2* __restrict__ x2, const float2* __restrict__ k2) {
    size_t i = (size_t)blockIdx.x * 256 + threadIdx.x;
    const size_t XN2 = (size_t)BH * LSEQ / 2;
    float2 v = (i < XN2) ? x2[i] : k2[i - XN2];
    ((__half2*)g_A)[i] = __floats2half2_rn(v.x, v.y);
}

// Wf[n][k] (K-major [N1,K1]): n=2f -> cos(2pi f k/8192); n=2f+1 -> -sin
__global__ void fill_Wf() {
    int idx = blockIdx.x * 256 + threadIdx.x;   // N1*K1/8 threads
    int n = idx >> 9, c = (idx & 511) << 3;
    int f = n >> 1, odd = n & 1;
    __half h[8];
#pragma unroll
    for (int j = 0; j < 8; j++) {
        int m = (f * (c + j)) & (NFFT - 1);
        float sv, cv;
        __sincosf((float)m * TWO_PI_OVER_N, &sv, &cv);
        h[j] = __float2half_rn(odd ? -sv : cv);
    }
    *(uint4*)(g_Wf + (size_t)n * K1 + c) = *(uint4*)h;
}

// Wi[n][k] (K-major [N2,K2]): k=2f -> cos(2pi f n/8192); k=2f+1 -> +sin
__global__ void fill_Wi() {
    int idx = blockIdx.x * 256 + threadIdx.x;   // N2*K2/8 threads
    int n = idx >> 7, c = (idx & 127) << 3;
    __half h[8];
#pragma unroll
    for (int j = 0; j < 4; j++) {
        int f = (c >> 1) + j;
        int m = (f * n) & (NFFT - 1);
        float sv, cv;
        __sincosf((float)m * TWO_PI_OVER_N, &sv, &cv);
        h[2 * j]     = __float2half_rn(cv);
        h[2 * j + 1] = __float2half_rn(sv);
    }
    *(uint4*)(g_Wi + (size_t)n * K2 + c) = *(uint4*)h;
}

// Z = alpha * X * K, stored as (Zr, -Zi) fp16; alpha=2/8192 (1/8192 at f=0).
// 4 bins per thread, uint4 vector I/O.
__global__ void pointwise_mul() {
    int idx = blockIdx.x * 256 + threadIdx.x;   // BH*NBINS/4 threads
    int r = idx >> 7, f4 = (idx & 127) << 2;
    int h = r % HDIM;
    uint4 xu = *(const uint4*)(g_X + (size_t)r * N1 + 2 * f4);
    uint4 ku = *(const uint4*)(g_X + (size_t)(BH + h) * N1 + 2 * f4);
    const __half2* xh = (const __half2*)&xu;
    const __half2* kh = (const __half2*)&ku;
    uint4 zu;
    __half2* zh = (__half2*)&zu;
#pragma unroll
    for (int j = 0; j < 4; j++) {
        float2 X = __half22float2(xh[j]);
        float2 K = __half22float2(kh[j]);
        float alpha = ((f4 + j) == 0) ? (1.0f / 8192.0f) : (2.0f / 8192.0f);
        float Zr = alpha * (X.x * K.x - X.y * K.y);
        float Zi = alpha * (X.x * K.y + X.y * K.x);
        zh[j] = __floats2half2_rn(Zr, -Zi);
    }
    *(uint4*)(g_Z + (size_t)r * K2 + 2 * f4) = zu;
}

// ================= tcgen05 cg2 path (sm_103a only) ============================
// C[M,N] = A[M,K] @ B[N,K]^T.  Cluster(2,1,1): M-tile 256 (128 rows/CTA),
// N-tile 512 via two N=256 cg2 MMAs (D cols 0 / 256), BK=64, 4-stage cp.async.
// Warps 0-6 producers, warp 7 MMA issuer (rank 0), all 8 warps epilogue.
constexpr int STG = 4;
constexpr int ATILE_B  = 128 * 64 * 2;                 // 16 KB
constexpr int BTILE_B  = 256 * 64 * 2;                 // 32 KB (this CTA's B half rows)
constexpr int STAGE_B  = ATILE_B + BTILE_B;            // 48 KB
constexpr int SMEM_DYN = 1024 + 1024 + STG * STAGE_B;  // 194 KB

#if HAS_TCGEN05
static constexpr uint64_t SMEM_DESC_BASE_SW128 =
    (uint64_t(2) << 61) | (uint64_t(1) << 46) | (uint64_t(64) << 32) | (uint64_t(1) << 16);
#define MAKE_SMEM_DESC(addr) (SMEM_DESC_BASE_SW128 | ((uint64_t)((addr) >> 4) & 0x3FFF))

#define TCGEN05_ALLOC_CG2(smem_addr, ncols) \
    asm volatile("tcgen05.alloc.cta_group::2.sync.aligned.shared::cta.b32 [%0], %1;" \
                 :: "r"((uint32_t)(smem_addr)), "r"((uint32_t)(ncols)) : "memory")
#define TCGEN05_DEALLOC_CG2(tmem, ncols) \
    asm volatile("tcgen05.dealloc.cta_group::2.sync.aligned.b32 %0, %1;" :: "r"(tmem), "r"((uint32_t)(ncols)))
#define TCGEN05_RELINQ_CG2() \
    asm volatile("tcgen05.relinquish_alloc_permit.cta_group::2.sync.aligned;")
#define TCGEN05_COMMIT_MC_CG2(mbar, mask) \
    asm volatile("tcgen05.commit.cta_group::2.mbarrier::arrive::one.shared::cluster.multicast::cluster.b64 [%0], %1;" \
                 :: "r"((uint32_t)(mbar)), "h"((uint16_t)(mask)) : "memory")
#define TCGEN05_FENCE_AFTER() asm volatile("tcgen05.fence::after_thread_sync;" ::: "memory")
#define TCGEN05_WAIT_LD()     asm volatile("tcgen05.wait::ld.sync.aligned;" ::: "memory")
#define TCGEN05_LD_X32(r, addr) \
    asm volatile("tcgen05.ld.sync.aligned.32x32b.x32.b32 "                         \
        "{%0, %1, %2, %3, %4, %5, %6, %7, %8, %9, %10, %11, %12, %13, %14, %15, "  \
        " %16, %17, %18, %19, %20, %21, %22, %23, %24, %25, %26, %27, %28, %29, %30, %31}, [%32];" \
        : "=r"((r)[0]),  "=r"((r)[1]),  "=r"((r)[2]),  "=r"((r)[3]),               \
          "=r"((r)[4]),  "=r"((r)[5]),  "=r"((r)[6]),  "=r"((r)[7]),               \
          "=r"((r)[8]),  "=r"((r)[9]),  "=r"((r)[10]), "=r"((r)[11]),              \
          "=r"((r)[12]), "=r"((r)[13]), "=r"((r)[14]), "=r"((r)[15]),              \
          "=r"((r)[16]), "=r"((r)[17]), "=r"((r)[18]), "=r"((r)[19]),              \
          "=r"((r)[20]), "=r"((r)[21]), "=r"((r)[22]), "=r"((r)[23]),              \
          "=r"((r)[24]), "=r"((r)[25]), "=r"((r)[26]), "=r"((r)[27]),              \
          "=r"((r)[28]), "=r"((r)[29]), "=r"((r)[30]), "=r"((r)[31])               \
        : "r"(addr))

__device__ __forceinline__ void mma_f16_ss_cg2(uint32_t d, uint64_t ad, uint64_t bd,
                                               uint32_t idesc, uint32_t enable) {
    asm volatile(
        "{\n\t.reg .pred p;\n\t"
        "setp.ne.u32 p, %4, 0;\n\t"
        "tcgen05.mma.cta_group::2.kind::f16 [%0], %1, %2, %3, "
        "{%5, %5, %5, %5, %5, %5, %5, %5}, p;\n\t}"
        :: "r"(d), "l"(ad), "l"(bd), "r"(idesc), "r"(enable), "r"(0u)
        : "memory");
}
#endif // HAS_TCGEN05

// WHICH=1: A = [x;k] fp32 (converted in producer), B=g_Wf, C=g_X (fp16), NN=1024, KK=4096
// WHICH=2: A = g_Z fp16 (cp.async),               B=g_Wi, C=outp (fp32), NN=4096, KK=1024
template <int KK, int WHICH>
__global__ void __launch_bounds__(256, 1) __cluster_dims__(2, 1, 1)
gemm_tc2(const float* __restrict__ xin, const float* __restrict__ kin, float* __restrict__ outp) {
#if HAS_TCGEN05
    extern __shared__ char smem[];
    constexpr int NN = (WHICH == 1) ? N1 : N2;
    constexpr int KT = KK / 64;
    const __half* __restrict__ Bsrc = (WHICH == 1) ? g_Wf : g_Wi;

    const uint32_t sb = (smem_u32(smem) + 1023u) & ~1023u;
    const uint32_t mb_full  = sb + 8;
    const uint32_t mb_empty = sb + 40;
    const uint32_t mb_done  = sb + 72;
    const uint32_t tb = sb + 1024;

    const int tid = threadIdx.x, wid = tid >> 5, lane = tid & 31;
    const uint32_t rank = cluster_rank();
    const int bn = blockIdx.x >> 1;
    const int mbase = blockIdx.y * 256 + (int)rank * 128;

    if (tid == 0) {
        for (int s = 0; s < STG; s++) {
            MBARRIER_INIT(mb_full + 8 * s, 14);  // 7 producer warps x 2 CTAs
            MBARRIER_INIT(mb_empty + 8 * s, 1);
        }
        MBARRIER_INIT(mb_done, 1);
    }
    if (wid == 4) { TCGEN05_ALLOC_CG2(sb, 512); TCGEN05_RELINQ_CG2(); }
    __syncthreads();
    uint32_t tmem;
    asm volatile("ld.shared.b32 %0, [%1];" : "=r"(tmem) : "r"(sb));
    CLUSTER_SYNC();

    if (wid < 7) {
        // ------------------------------ producers (224 threads) --------------
        const float* asrc32 = nullptr;
        const __half* asrc16 = nullptr;
        if (WHICH == 1)
            asrc32 = (mbase < BH) ? xin + (size_t)mbase * K1
                                  : kin + (size_t)(mbase - BH) * K1;
        else
            asrc16 = g_Z + (size_t)mbase * KK;

        for (int kt = 0; kt < KT; kt++) {
            const int s = kt & 3;
            MBARRIER_WAIT_PARITY(mb_empty + 8 * s, ((kt >> 2) + 1) & 1);
            const int k0 = kt * 64;
            const uint32_t sA = tb + s * STAGE_B;
            const uint32_t sB = sA + ATILE_B;
            // 3072 16B-chunks/stage: [0,1024) A, [1024,3072) B (two 1024 groups)
#pragma unroll
            for (int i = 0; i < 14; i++) {
                int ci = tid + i * 224;
                if (ci >= 3072) break;
                if (ci < 1024) {
                    int r = ci >> 3, c8 = ci & 7;
                    if (WHICH == 1) {
                        const float4* p = (const float4*)(asrc32 + (size_t)r * K1 + k0 + c8 * 8);
                        float4 v0 = p[0], v1 = p[1];
                        __half2 a0 = __floats2half2_rn(v0.x, v0.y);
                        __half2 a1 = __floats2half2_rn(v0.z, v0.w);
                        __half2 a2 = __floats2half2_rn(v1.x, v1.y);
                        __half2 a3 = __floats2half2_rn(v1.z, v1.w);
                        asm volatile("st.shared.v4.b32 [%0], {%1,%2,%3,%4};"
                            :: "r"(sA + SWZ(r * 128 + c8 * 16)),
                               "r"(*(uint32_t*)&a0), "r"(*(uint32_t*)&a1),
                               "r"(*(uint32_t*)&a2), "r"(*(uint32_t*)&a3) : "memory");
                    } else {
                        cp16(sA + SWZ(r * 128 + c8 * 16), asrc16 + (size_t)r * KK + k0 + c8 * 8);
                    }
                } else {
                    int cj = ci - 1024;
                    int g = cj >> 10, w = cj & 1023;
                    int r = w >> 3, c8 = w & 7;
                    const __half* bg = Bsrc + (size_t)(bn * 512 + g * 256 + (int)rank * 128 + r) * KK + k0;
                    cp16(sB + g * 16384 + SWZ(r * 128 + c8 * 16), bg + c8 * 8);
                }
            }
            cp_commit();
            if (kt >= 1) {
                cp_wait<1>();
                asm volatile("fence.proxy.async.shared::cta;" ::: "memory");
                if (lane == 0) MBARRIER_ARRIVE_LEADER(mb_full + 8 * ((kt - 1) & 3));
            }
        }
        cp_wait<0>();
        asm volatile("fence.proxy.async.shared::cta;" ::: "memory");
        if (lane == 0) MBARRIER_ARRIVE_LEADER(mb_full + 8 * ((KT - 1) & 3));
    } else if (rank == 0 && tid == 224) {
        // ------------------------------ MMA issuer ---------------------------
        const uint32_t idesc = (1u << 4) | (32u << 17) | (16u << 24);  // F32, N=256, M=256
        for (int kt = 0; kt < KT; kt++) {
            const int s = kt & 3;
            MBARRIER_WAIT_PARITY(mb_full + 8 * s, (kt >> 2) & 1);
            const uint64_t ad  = MAKE_SMEM_DESC(tb + s * STAGE_B);
            const uint64_t bd0 = MAKE_SMEM_DESC(tb + s * STAGE_B + ATILE_B);
            const uint64_t bd1 = bd0 + 1024;
#pragma unroll
            for (int j = 0; j < 4; j++) {
                uint32_t en = (uint32_t)((kt | j) != 0);
                mma_f16_ss_cg2(tmem,       ad + 2 * j, bd0 + 2 * j, idesc, en);
                mma_f16_ss_cg2(tmem + 256, ad + 2 * j, bd1 + 2 * j, idesc, en);
            }
            TCGEN05_COMMIT_MC_CG2(mb_empty + 8 * s, 3);
        }
        TCGEN05_COMMIT_MC_CG2(mb_done, 3);
    }

    // ------------------------------ epilogue: all 8 warps ---------------------
    __syncwarp();
    MBARRIER_WAIT_PARITY(mb_done, 0);
    TCGEN05_FENCE_AFTER();
    {
        const int rowl = (wid & 3) * 32 + lane;      // subpartition row
        const int cb = (wid >> 2) * 256;             // column half
        const int grow = mbase + rowl;
#pragma unroll
        for (int c0 = 0; c0 < 256; c0 += 32) {
            uint32_t r[32];
            TCGEN05_LD_X32(r, tmem + cb + c0);
            TCGEN05_WAIT_LD();
            if (WHICH == 1) {
                uint4 u[2];
                __half2* hp = (__half2*)u;
#pragma unroll
                for (int q = 0; q < 8; q++)
                    hp[q] = __floats2half2_rn(__uint_as_float(r[2 * q]), __uint_as_float(r[2 * q + 1]));
                __half* dst = g_X + (size_t)grow * NN + bn * 512 + cb + c0;
                *(uint4*)(dst)     = u[0];
                *(uint4*)(dst + 8) = u[1];
                uint4 v[2];
                __half2* vp = (__half2*)v;
#pragma unroll
                for (int q = 0; q < 8; q++)
                    vp[q] = __floats2half2_rn(__uint_as_float(r[16 + 2 * q]), __uint_as_float(r[17 + 2 * q]));
                *(uint4*)(dst + 16) = v[0];
                *(uint4*)(dst + 24) = v[1];
            } else {
                float* dst = outp + (size_t)grow * NN + bn * 512 + cb + c0;
#pragma unroll
                for (int q = 0; q < 8; q++) {
                    float4 v = make_float4(__uint_as_float(r[4 * q + 0]), __uint_as_float(r[4 * q + 1]),
                                           __uint_as_float(r[4 * q + 2]), __uint_as_float(r[4 * q + 3]));
                    *(float4*)(dst + 4 * q) = v;
                }
            }
        }
    }

    __syncthreads();
    if (wid == 4) TCGEN05_DEALLOC_CG2(tmem, 512);
    CLUSTER_SYNC();
#endif // HAS_TCGEN05
}

// ================= HMMA fallback (compiles everywhere) ========================
__device__ __forceinline__ void ldsm4(uint32_t& r0, uint32_t& r1, uint32_t& r2, uint32_t& r3, uint32_t a) {
    asm volatile("ldmatrix.sync.aligned.m8n8.x4.shared.b16 {%0,%1,%2,%3}, [%4];\n"
                 : "=r"(r0), "=r"(r1), "=r"(r2), "=r"(r3) : "r"(a));
}
__device__ __forceinline__ void mma16816(float* c, uint32_t a0, uint32_t a1, uint32_t a2, uint32_t a3,
                                         uint32_t b0, uint32_t b1) {
    asm volatile(
        "mma.sync.aligned.m16n8k16.row.col.f32.f16.f16.f32 "
        "{%0,%1,%2,%3}, {%4,%5,%6,%7}, {%8,%9}, {%0,%1,%2,%3};\n"
        : "+f"(c[0]), "+f"(c[1]), "+f"(c[2]), "+f"(c[3])
        : "r"(a0), "r"(a1), "r"(a2), "r"(a3), "r"(b0), "r"(b1));
}

template <int MM, int NN, int KK, int WHICH>
__global__ void __launch_bounds__(256, 2) gemm_hmma(float* __restrict__ outp) {
    const __half* __restrict__ A = (WHICH == 1) ? g_A  : g_Z;
    const __half* __restrict__ B = (WHICH == 1) ? g_Wf : g_Wi;

    constexpr int FBM = 128, FBN = 128, FBK = 32;
    constexpr int LDT = FBK + 8;
    __shared__ __align__(16) __half As[2][FBM * LDT];
    __shared__ __align__(16) __half Bs[2][FBN * LDT];

    const int tid = threadIdx.x, lane = tid & 31, wid = tid >> 5;
    const int wm = wid & 3, wn = wid >> 2;
    const int bm = blockIdx.y * FBM, bn = blockIdx.x * FBN;

    float acc[2][8][4];
#pragma unroll
    for (int i = 0; i < 2; i++)
#pragma unroll
        for (int j = 0; j < 8; j++)
#pragma unroll
            for (int q = 0; q < 4; q++) acc[i][j][q] = 0.f;

    const int trow = tid >> 2, tcol = (tid & 3) << 3;
    auto load_tile = [&](int kt, int buf) {
        const int k0 = kt * FBK;
        const __half* ag = A + (size_t)(bm + trow) * KK + k0 + tcol;
        cp16(smem_u32(&As[buf][trow * LDT + tcol]), ag);
        cp16(smem_u32(&As[buf][(trow + 64) * LDT + tcol]), ag + (size_t)64 * KK);
        const __half* bg = B + (size_t)(bn + trow) * KK + k0 + tcol;
        cp16(smem_u32(&Bs[buf][trow * LDT + tcol]), bg);
        cp16(smem_u32(&Bs[buf][(trow + 64) * LDT + tcol]), bg + (size_t)64 * KK);
        cp_commit();
    };

    load_tile(0, 0);
    constexpr int KT = KK / FBK;
    for (int kt = 0; kt < KT; kt++) {
        const int buf = kt & 1;
        if (kt + 1 < KT) { load_tile(kt + 1, buf ^ 1); cp_wait<1>(); }
        else            { cp_wait<0>(); }
        __syncthreads();
#pragma unroll
        for (int ks = 0; ks < 2; ks++) {
            uint32_t a[2][4], b[4][4];
#pragma unroll
            for (int mt = 0; mt < 2; mt++) {
                int r = wm * 32 + mt * 16 + (lane & 15);
                int c = ks * 16 + ((lane >> 4) << 3);
                ldsm4(a[mt][0], a[mt][1], a[mt][2], a[mt][3], smem_u32(&As[buf][r * LDT + c]));
            }
#pragma unroll
            for (int nt = 0; nt < 4; nt++) {
                int r = wn * 64 + nt * 16 + (lane & 15);
                int c = ks * 16 + ((lane >> 4) << 3);
                ldsm4(b[nt][0], b[nt][1], b[nt][2], b[nt][3], smem_u32(&Bs[buf][r * LDT + c]));
            }
#pragma unroll
            for (int mt = 0; mt < 2; mt++)
#pragma unroll
                for (int nt = 0; nt < 8; nt++)
                    mma16816(acc[mt][nt], a[mt][0], a[mt][1], a[mt][2], a[mt][3],
                             b[nt >> 1][nt & 1], b[nt >> 1][(nt & 1) + 2]);
        }
        __syncthreads();
    }
#pragma unroll
    for (int mt = 0; mt < 2; mt++)
#pragma unroll
        for (int nt = 0; nt < 8; nt++) {
            int row = bm + wm * 32 + mt * 16 + (lane >> 2);
            int col = bn + wn * 64 + nt * 8 + ((lane & 3) << 1);
            if (WHICH == 1) {
                g_X[(size_t)row * NN + col]           = __float2half_rn(acc[mt][nt][0]);
                g_X[(size_t)row * NN + col + 1]       = __float2half_rn(acc[mt][nt][1]);
                g_X[(size_t)(row + 8) * NN + col]     = __float2half_rn(acc[mt][nt][2]);
                g_X[(size_t)(row + 8) * NN + col + 1] = __float2half_rn(acc[mt][nt][3]);
            } else {
                outp[(size_t)row * NN + col]           = acc[mt][nt][0];
                outp[(size_t)row * NN + col + 1]       = acc[mt][nt][1];
                outp[(size_t)(row + 8) * NN + col]     = acc[mt][nt][2];
                outp[(size_t)(row + 8) * NN + col + 1] = acc[mt][nt][3];
            }
        }
}

// ---------------- launch -------------------------------------------------------
extern "C" void kernel_launch(void* const* d_in, const int* in_sizes, int n_in,
                              void* d_out, int out_size) {
    const float* x = (const float*)d_in[0];
    const float* k = (const float*)d_in[1];
    float* out = (float*)d_out;

    cudaFuncAttributes fa{};
    bool use_tc = (cudaFuncGetAttributes(&fa, (const void*)gemm_tc2<K1, 1>) == cudaSuccess)
                  && (fa.numRegs >= 40);

    fill_Wf<<<(N1 * K1 / 8) / 256, 256>>>();
    fill_Wi<<<(N2 * K2 / 8) / 256, 256>>>();

    if (use_tc) {
        cudaFuncSetAttribute((const void*)gemm_tc2<K1, 1>,
                             cudaFuncAttributeMaxDynamicSharedMemorySize, SMEM_DYN);
        cudaFuncSetAttribute((const void*)gemm_tc2<K2, 2>,
                             cudaFuncAttributeMaxDynamicSharedMemorySize, SMEM_DYN);
        gemm_tc2<K1, 1><<<dim3(2 * N1 / 512, M1 / 256), 256, SMEM_DYN>>>(x, k, nullptr);
        pointwise_mul<<<(BH * NBINS / 4) / 256, 256>>>();
        gemm_tc2<K2, 2><<<dim3(2 * N2 / 512, M2 / 256), 256, SMEM_DYN>>>(x, k, out);
    } else {
        convert_inputs<<<(M1 * K1 / 2) / 256, 256>>>((const float2*)x, (const float2*)k);
        gemm_hmma<M1, N1, K1, 1><<<dim3(N1 / 128, M1 / 128), 256>>>(nullptr);
        pointwise_mul<<<(BH * NBINS / 4) / 256, 256>>>();
        gemm_hmma<M2, N2, K2, 2><<<dim3(N2 / 128, M2 / 128), 256>>>(out);
    }
}